// round 1
// baseline (speedup 1.0000x reference)
#include <cuda_runtime.h>
#include <math.h>

#define B_ 4
#define T_ 1024
#define D_ 1024
#define H_ 16
#define K_ 64
#define BT_ (B_*T_)        // 4096
#define BTD (BT_*D_)       // 4194304

// ---------------- scratch (static device globals; no runtime alloc) --------
__device__ float g_dx[BTD];
__device__ float g_xmix[BTD];
__device__ float g_xxx[BT_*160];
__device__ float g_xm[5][BTD];          // xw,xk,xv,xr,xg
__device__ float g_r[BTD], g_k[BTD], g_v[BTD], g_gt[BTD], g_w[BTD];
__device__ float g_wtmp[BT_*64];
__device__ float g_rf[BTD], g_kf[BTD], g_rb[BTD], g_kb[BTD], g_vh[BTD];
__device__ float g_yh[BTD];
__device__ float g_yg[BTD];

enum { EP_NONE=0, EP_TANH=1, EP_SILU=2, EP_BIAS=3, EP_MIX=4 };

// ---------------- prep: dxprev + xmix ---------------------------------------
__global__ void prep_kernel(const float* __restrict__ x,
                            const float* __restrict__ maa_x) {
    int idx = blockIdx.x*256 + threadIdx.x;
    if (idx >= BTD) return;
    int d = idx & (D_-1);
    int t = (idx >> 10) & (T_-1);
    float xc = x[idx];
    float left  = (t > 0)     ? x[idx - D_] : 0.f;
    float right = (t < T_-1)  ? x[idx + D_] : 0.f;
    float dx = 0.5f*(left + right) - xc;
    g_dx[idx]   = dx;
    g_xmix[idx] = xc + dx * maa_x[d];
}

// ---------------- generic tiled SGEMM: C = A * op(B), with epilogues --------
// TB=false: B is (Kd x N) row-major (ldb = row stride). C[m,n]=sum_k A[m,k]*B[k,n]
// TB=true : B is (N x Kd) row-major (NT / weight @ W^T). C[m,n]=sum_k A[m,k]*B[n,k]
template<int EP, bool TB>
__global__ __launch_bounds__(256)
void sgemm_kernel(const float* __restrict__ A, int lda,
                  const float* __restrict__ Bm, int ldb,
                  float* __restrict__ C, int ldc,
                  int M, int N, int Kd,
                  const float* __restrict__ bias,
                  const float* __restrict__ xbase,
                  const float* __restrict__ dxp,
                  const float* __restrict__ maa)
{
    __shared__ float As[16][68];
    __shared__ float Bs[16][68];
    const int tid = threadIdx.x;
    const int tx = tid & 15, ty = tid >> 4;
    const int m0 = blockIdx.y * 64, n0 = blockIdx.x * 64;
    float acc[4][4];
    #pragma unroll
    for (int i=0;i<4;i++)
        #pragma unroll
        for (int j=0;j<4;j++) acc[i][j]=0.f;

    for (int k0 = 0; k0 < Kd; k0 += 16) {
        #pragma unroll
        for (int it=0; it<4; it++) {
            int e = tid + it*256;
            int col = e & 15, row = e >> 4;
            int gm = m0 + row, gk = k0 + col;
            As[col][row] = (gm < M && gk < Kd) ? A[(size_t)gm*lda + gk] : 0.f;
        }
        #pragma unroll
        for (int it=0; it<4; it++) {
            int e = tid + it*256;
            int kk, nn;
            if (TB) { kk = e & 15; nn = e >> 4; } else { nn = e & 63; kk = e >> 6; }
            int gk = k0 + kk, gn = n0 + nn;
            float v = 0.f;
            if (gn < N && gk < Kd)
                v = TB ? Bm[(size_t)gn*ldb + gk] : Bm[(size_t)gk*ldb + gn];
            Bs[kk][nn] = v;
        }
        __syncthreads();
        #pragma unroll
        for (int kk=0; kk<16; kk++) {
            float a[4], b[4];
            #pragma unroll
            for (int i=0;i<4;i++) a[i] = As[kk][ty*4+i];
            #pragma unroll
            for (int j=0;j<4;j++) b[j] = Bs[kk][tx*4+j];
            #pragma unroll
            for (int i=0;i<4;i++)
                #pragma unroll
                for (int j=0;j<4;j++) acc[i][j] = fmaf(a[i], b[j], acc[i][j]);
        }
        __syncthreads();
    }
    #pragma unroll
    for (int i=0;i<4;i++) {
        int m = m0 + ty*4 + i;
        if (m >= M) continue;
        #pragma unroll
        for (int j=0;j<4;j++) {
            int n = n0 + tx*4 + j;
            if (n >= N) continue;
            float v = acc[i][j];
            if (EP == EP_TANH)      v = tanhf(v);
            else if (EP == EP_SILU) v = v / (1.f + expf(-v));
            else if (EP == EP_BIAS) v = v + bias[n];
            else if (EP == EP_MIX) {
                size_t o = (size_t)m*ldc + n;
                v = xbase[o] + dxp[o]*(maa[n] + v);
            }
            C[(size_t)m*ldc + n] = v;
        }
    }
}

// ---------------- per-head cumsum + exp-factor precompute -------------------
__global__ __launch_bounds__(1024)
void headprep_kernel() {
    int bh = blockIdx.x;
    int b = bh >> 4, h = bh & 15;
    int tid = threadIdx.x;
    int c = tid >> 6, kx = tid & 63;
    __shared__ float csum[16][64];
    __shared__ float w512[64], shf[64], shb[64];
    const size_t ibase = (size_t)b*T_*D_ + (size_t)h*K_ + kx; // + t*D_
    float s = 0.f;
    for (int tt=0; tt<64; tt++) {
        int t = c*64 + tt;
        float wv = -expf(g_w[ibase + (size_t)t*D_]);
        if (t == 512) w512[kx] = wv;
        s += wv;
    }
    csum[c][kx] = s;
    __syncthreads();
    if (tid < 64) {
        float run = 0.f;
        #pragma unroll
        for (int cc=0; cc<16; cc++) {
            if (cc == 8) shb[tid] = run;
            float tmp = csum[cc][tid];
            csum[cc][tid] = run;        // exclusive chunk prefix
            run += tmp;
        }
        shf[tid] = shb[tid] + w512[tid];  // inclusive cumsum at t=512
    }
    __syncthreads();
    float cs = csum[c][kx];
    float sf = shf[kx], sb = shb[kx];
    size_t obase = (size_t)bh*T_*K_ + kx;
    for (int tt=0; tt<64; tt++) {
        int t = c*64 + tt;
        size_t gi = ibase + (size_t)t*D_;
        float wv = -expf(g_w[gi]);
        float cprev = cs;
        cs += wv;
        float cf = fminf(fmaxf(cs    - sf, -60.f), 60.f);
        float cb = fminf(fmaxf(cprev - sb, -60.f), 60.f);
        float rr = g_r[gi], kk = g_k[gi], vv = g_v[gi];
        size_t go = obase + (size_t)t*K_;
        g_rf[go] = rr * expf( cf);
        g_kf[go] = kk * expf(-cf);
        g_rb[go] = rr * expf(-cb);
        g_kb[go] = kk * expf( cb);
        g_vh[go] = vv;
    }
}

// ---------------- bidirectional quadratic attention, 64x64 tiles ------------
__global__ __launch_bounds__(256)
void attn_kernel() {
    extern __shared__ float sm[];
    typedef float row_t[65];
    row_t* Rf = (row_t*)sm;
    row_t* Rb = Rf + 64;
    row_t* Kf = Rb + 64;
    row_t* Kb = Kf + 64;
    row_t* Vs = Kb + 64;
    row_t* Ss = Vs + 64;

    int bh = blockIdx.x, it = blockIdx.y;
    int tid = threadIdx.x, tx = tid & 15, ty = tid >> 4;
    size_t base = (size_t)bh * T_ * K_;
    int i0 = it * 64;

    for (int e = tid; e < 4096; e += 256) {
        int r = e >> 6, cc = e & 63;
        size_t g = base + (size_t)(i0 + r)*K_ + cc;
        Rf[r][cc] = g_rf[g];
        Rb[r][cc] = g_rb[g];
    }
    float acc[4][4];
    #pragma unroll
    for (int i=0;i<4;i++)
        #pragma unroll
        for (int j=0;j<4;j++) acc[i][j]=0.f;

    for (int jt = 0; jt < 16; jt++) {
        __syncthreads();
        int j0 = jt * 64;
        for (int e = tid; e < 4096; e += 256) {
            int r = e >> 6, cc = e & 63;
            size_t g = base + (size_t)(j0 + r)*K_ + cc;
            Vs[r][cc] = g_vh[g];
            if (jt <= it) Kf[r][cc] = g_kf[g];
            if (jt >= it) Kb[r][cc] = g_kb[g];
        }
        __syncthreads();

        float S[4][4];
        #pragma unroll
        for (int i=0;i<4;i++)
            #pragma unroll
            for (int j=0;j<4;j++) S[i][j]=0.f;

        if (jt <= it) {               // forward/causal factors
            #pragma unroll 8
            for (int kk=0; kk<64; kk++) {
                float a[4], b[4];
                #pragma unroll
                for (int i=0;i<4;i++) a[i] = Rf[ty*4+i][kk];
                #pragma unroll
                for (int j=0;j<4;j++) b[j] = Kf[tx*4+j][kk];
                #pragma unroll
                for (int i=0;i<4;i++)
                    #pragma unroll
                    for (int j=0;j<4;j++) S[i][j] = fmaf(a[i], b[j], S[i][j]);
            }
        } else {                      // backward factors
            #pragma unroll 8
            for (int kk=0; kk<64; kk++) {
                float a[4], b[4];
                #pragma unroll
                for (int i=0;i<4;i++) a[i] = Rb[ty*4+i][kk];
                #pragma unroll
                for (int j=0;j<4;j++) b[j] = Kb[tx*4+j][kk];
                #pragma unroll
                for (int i=0;i<4;i++)
                    #pragma unroll
                    for (int j=0;j<4;j++) S[i][j] = fmaf(a[i], b[j], S[i][j]);
            }
        }
        if (jt == it) {               // diagonal tile: compute backward, select
            float Sb[4][4];
            #pragma unroll
            for (int i=0;i<4;i++)
                #pragma unroll
                for (int j=0;j<4;j++) Sb[i][j]=0.f;
            #pragma unroll 8
            for (int kk=0; kk<64; kk++) {
                float a[4], b[4];
                #pragma unroll
                for (int i=0;i<4;i++) a[i] = Rb[ty*4+i][kk];
                #pragma unroll
                for (int j=0;j<4;j++) b[j] = Kb[tx*4+j][kk];
                #pragma unroll
                for (int i=0;i<4;i++)
                    #pragma unroll
                    for (int j=0;j<4;j++) Sb[i][j] = fmaf(a[i], b[j], Sb[i][j]);
            }
            #pragma unroll
            for (int i=0;i<4;i++)
                #pragma unroll
                for (int j=0;j<4;j++)
                    if (ty*4+i < tx*4+j) S[i][j] = Sb[i][j];
        }
        #pragma unroll
        for (int i=0;i<4;i++)
            #pragma unroll
            for (int j=0;j<4;j++) Ss[ty*4+i][tx*4+j] = S[i][j];
        __syncthreads();

        #pragma unroll 8
        for (int j=0; j<64; j++) {
            float a[4], b[4];
            #pragma unroll
            for (int i=0;i<4;i++) a[i] = Ss[ty*4+i][j];
            #pragma unroll
            for (int jj=0;jj<4;jj++) b[jj] = Vs[j][tx*4+jj];
            #pragma unroll
            for (int i=0;i<4;i++)
                #pragma unroll
                for (int jj=0;jj<4;jj++) acc[i][jj] = fmaf(a[i], b[jj], acc[i][jj]);
        }
    }
    #pragma unroll
    for (int i=0;i<4;i++)
        #pragma unroll
        for (int j=0;j<4;j++)
            g_yh[base + (size_t)(i0 + ty*4+i)*K_ + tx*4+j] = acc[i][j];
}

// ---------------- group-norm (per head, K=64) + scale/bias + gate -----------
__global__ __launch_bounds__(512)
void ln_gate_kernel(const float* __restrict__ ln_w,
                    const float* __restrict__ ln_b) {
    int row = blockIdx.x;          // b*T + t
    int b = row >> 10, t = row & (T_-1);
    int h = threadIdx.x >> 5;      // warp = head
    int lane = threadIdx.x & 31;
    size_t base = (((size_t)b*H_ + h)*T_ + t)*K_;
    float v0 = g_yh[base + lane*2];
    float v1 = g_yh[base + lane*2 + 1];
    float s = v0 + v1;
    #pragma unroll
    for (int off=16; off>0; off>>=1) s += __shfl_xor_sync(0xffffffffu, s, off);
    float mu = s * (1.f/64.f);
    float d0 = v0 - mu, d1 = v1 - mu;
    float sq = d0*d0 + d1*d1;
    #pragma unroll
    for (int off=16; off>0; off>>=1) sq += __shfl_xor_sync(0xffffffffu, sq, off);
    float inv = rsqrtf(sq*(1.f/64.f) + 6.4e-4f);
    int d = h*K_ + lane*2;
    size_t o = (size_t)row*D_ + d;
    float y0 = (d0*inv)*ln_w[d]   + ln_b[d];
    float y1 = (d1*inv)*ln_w[d+1] + ln_b[d+1];
    g_yg[o]   = y0 * g_gt[o];
    g_yg[o+1] = y1 * g_gt[o+1];
}

// ---------------- host launch ------------------------------------------------
extern "C" void kernel_launch(void* const* d_in, const int* in_sizes, int n_in,
                              void* d_out, int out_size) {
    const float* x        = (const float*)d_in[0];
    const float* maa_x    = (const float*)d_in[1];
    const float* maa_w    = (const float*)d_in[2];
    const float* maa_k    = (const float*)d_in[3];
    const float* maa_v    = (const float*)d_in[4];
    const float* maa_r    = (const float*)d_in[5];
    const float* maa_g    = (const float*)d_in[6];
    const float* maa_w1   = (const float*)d_in[7];   // (D, 160)
    const float* maa_w2   = (const float*)d_in[8];   // (5, 32, D)
    const float* tdecay   = (const float*)d_in[9];   // (1,1,D)
    const float* dec_w1   = (const float*)d_in[10];  // (D, 64)
    const float* dec_w2   = (const float*)d_in[11];  // (64, D)
    const float* W_r      = (const float*)d_in[12];
    const float* W_k      = (const float*)d_in[13];
    const float* W_v      = (const float*)d_in[14];
    const float* W_g      = (const float*)d_in[15];
    const float* W_o      = (const float*)d_in[16];
    const float* ln_w     = (const float*)d_in[17];
    const float* ln_b     = (const float*)d_in[18];
    float* out = (float*)d_out;

    float *p_dx, *p_xmix, *p_xxx, *p_xm, *p_r, *p_k, *p_v, *p_gt, *p_w, *p_wtmp, *p_yg;
    cudaGetSymbolAddress((void**)&p_dx,   g_dx);
    cudaGetSymbolAddress((void**)&p_xmix, g_xmix);
    cudaGetSymbolAddress((void**)&p_xxx,  g_xxx);
    cudaGetSymbolAddress((void**)&p_xm,   g_xm);
    cudaGetSymbolAddress((void**)&p_r,    g_r);
    cudaGetSymbolAddress((void**)&p_k,    g_k);
    cudaGetSymbolAddress((void**)&p_v,    g_v);
    cudaGetSymbolAddress((void**)&p_gt,   g_gt);
    cudaGetSymbolAddress((void**)&p_w,    g_w);
    cudaGetSymbolAddress((void**)&p_wtmp, g_wtmp);
    cudaGetSymbolAddress((void**)&p_yg,   g_yg);

    // 1) dxprev + xmix
    prep_kernel<<<(BTD+255)/256, 256>>>(x, maa_x);

    // 2) xxx = tanh(xmix @ maa_w1)    M=4096,N=160,K=1024 (NN)
    sgemm_kernel<EP_TANH,false><<<dim3(3,64), 256>>>(
        p_xmix, D_, maa_w1, 160, p_xxx, 160, BT_, 160, D_,
        nullptr, nullptr, nullptr, nullptr);

    // 3) x{w,k,v,r,g} = x + dxprev*(maa_f + xxx_f @ w2_f)   (NN, K=32, fused)
    const float* maas[5] = {maa_w, maa_k, maa_v, maa_r, maa_g};
    for (int f = 0; f < 5; f++) {
        sgemm_kernel<EP_MIX,false><<<dim3(16,64), 256>>>(
            p_xxx + f*32, 160, maa_w2 + (size_t)f*32*D_, D_,
            p_xm + (size_t)f*BTD, D_, BT_, D_, 32,
            nullptr, x, p_dx, maas[f]);
    }

    // 4) big projections (NT against W[D,D])
    sgemm_kernel<EP_NONE,true><<<dim3(16,64), 256>>>(
        p_xm + 3*(size_t)BTD, D_, W_r, D_, p_r, D_, BT_, D_, D_,
        nullptr, nullptr, nullptr, nullptr);
    sgemm_kernel<EP_NONE,true><<<dim3(16,64), 256>>>(
        p_xm + 1*(size_t)BTD, D_, W_k, D_, p_k, D_, BT_, D_, D_,
        nullptr, nullptr, nullptr, nullptr);
    sgemm_kernel<EP_NONE,true><<<dim3(16,64), 256>>>(
        p_xm + 2*(size_t)BTD, D_, W_v, D_, p_v, D_, BT_, D_, D_,
        nullptr, nullptr, nullptr, nullptr);
    sgemm_kernel<EP_SILU,true><<<dim3(16,64), 256>>>(
        p_xm + 4*(size_t)BTD, D_, W_g, D_, p_gt, D_, BT_, D_, D_,
        nullptr, nullptr, nullptr, nullptr);

    // 5) w = time_decay + tanh(xw @ dec_w1) @ dec_w2
    sgemm_kernel<EP_TANH,false><<<dim3(1,64), 256>>>(
        p_xm + 0*(size_t)BTD, D_, dec_w1, 64, p_wtmp, 64, BT_, 64, D_,
        nullptr, nullptr, nullptr, nullptr);
    sgemm_kernel<EP_BIAS,false><<<dim3(16,64), 256>>>(
        p_wtmp, 64, dec_w2, D_, p_w, D_, BT_, D_, 64,
        tdecay, nullptr, nullptr, nullptr);

    // 6) cumsum + exp factors into head layout
    headprep_kernel<<<B_*H_, 1024>>>();

    // 7) bidirectional attention
    static const int ATTN_SMEM = 6*64*65*4;   // 99840 B
    cudaFuncSetAttribute(attn_kernel,
                         cudaFuncAttributeMaxDynamicSharedMemorySize, ATTN_SMEM);
    attn_kernel<<<dim3(B_*H_, 16), 256, ATTN_SMEM>>>();

    // 8) group-norm + gate
    ln_gate_kernel<<<BT_, 512>>>(ln_w, ln_b);

    // 9) out = yg @ W_o^T
    sgemm_kernel<EP_NONE,true><<<dim3(16,64), 256>>>(
        p_yg, D_, W_o, D_, out, D_, BT_, D_, D_,
        nullptr, nullptr, nullptr, nullptr);
}

// round 2
// speedup vs baseline: 2.1027x; 2.1027x over previous
#include <cuda_runtime.h>
#include <math.h>

#define B_ 4
#define T_ 1024
#define D_ 1024
#define H_ 16
#define K_ 64
#define BT_ (B_*T_)        // 4096
#define BTD (BT_*D_)       // 4194304

// ---------------- scratch (static device globals; no runtime alloc) --------
__device__ float g_dx[BTD];
__device__ float g_xmix[BTD];
__device__ float g_xxx[BT_*160];
__device__ float g_xm[5][BTD];          // xw,xk,xv,xr,xg
__device__ float g_r[BTD], g_k[BTD], g_v[BTD], g_gt[BTD], g_w[BTD];
__device__ float g_wtmp[BT_*64];
__device__ float g_rf[BTD], g_kf[BTD], g_rb[BTD], g_kb[BTD], g_vh[BTD];
__device__ float g_yh[BTD];
__device__ float g_yg[BTD];

enum { EP_NONE=0, EP_TANH=1, EP_SILU=2, EP_BIAS=3, EP_MIX=4 };

// ---------------- tf32 helpers ----------------------------------------------
__device__ __forceinline__ unsigned tf32_of(float x) {
    unsigned u; asm("cvt.rna.tf32.f32 %0, %1;" : "=r"(u) : "f"(x)); return u;
}
__device__ __forceinline__ float tf32f(float x) {
    return __uint_as_float(tf32_of(x));
}
__device__ __forceinline__ void mma_tf32(float c[4], unsigned a0, unsigned a1,
                                         unsigned a2, unsigned a3,
                                         unsigned b0, unsigned b1) {
    asm volatile(
        "mma.sync.aligned.m16n8k8.row.col.f32.tf32.tf32.f32 "
        "{%0,%1,%2,%3},{%4,%5,%6,%7},{%8,%9},{%0,%1,%2,%3};"
        : "+f"(c[0]), "+f"(c[1]), "+f"(c[2]), "+f"(c[3])
        : "r"(a0), "r"(a1), "r"(a2), "r"(a3), "r"(b0), "r"(b1));
}

// ---------------- prep: dxprev + xmix ---------------------------------------
__global__ void prep_kernel(const float* __restrict__ x,
                            const float* __restrict__ maa_x) {
    int idx = blockIdx.x*256 + threadIdx.x;
    if (idx >= BTD) return;
    int d = idx & (D_-1);
    int t = (idx >> 10) & (T_-1);
    float xc = x[idx];
    float left  = (t > 0)     ? x[idx - D_] : 0.f;
    float right = (t < T_-1)  ? x[idx + D_] : 0.f;
    float dx = 0.5f*(left + right) - xc;
    g_dx[idx]   = dx;
    g_xmix[idx] = xc + dx * maa_x[d];
}

// ---------------- tf32 tensor-core GEMM: C = A * op(B), with epilogues ------
// M must be a multiple of 128, Kd a multiple of 16. N guarded.
// TB=false: B is (Kd x N) row-major. TB=true: B is (N x Kd) row-major (NT).
template<int EP, bool TB>
__global__ __launch_bounds__(256)
void mma_gemm(const float* __restrict__ A, int lda,
              const float* __restrict__ Bm, int ldb,
              float* __restrict__ C, int ldc,
              int M, int N, int Kd,
              const float* __restrict__ bias,
              const float* __restrict__ xbase,
              const float* __restrict__ dxp,
              const float* __restrict__ maa)
{
    __shared__ float As[128][20];   // [m][k], stride 20 -> conflict-free frags
    __shared__ float Bs[64][20];    // [n][k]
    const int tid  = threadIdx.x;
    const int lane = tid & 31, w = tid >> 5;
    const int g = lane >> 2, t4 = lane & 3;
    const int m0 = blockIdx.y * 128, n0 = blockIdx.x * 64;
    const int mw = w * 16;

    float acc[8][4];
    #pragma unroll
    for (int i=0;i<8;i++)
        #pragma unroll
        for (int j=0;j<4;j++) acc[i][j]=0.f;

    for (int k0 = 0; k0 < Kd; k0 += 16) {
        // A: 128x16, each thread 8 floats (two float4)
        {
            int r = tid >> 1, c = (tid & 1) * 8;
            const float* ap = A + (size_t)(m0 + r) * lda + k0 + c;
            float4 v0 = *(const float4*)(ap);
            float4 v1 = *(const float4*)(ap + 4);
            As[r][c+0]=tf32f(v0.x); As[r][c+1]=tf32f(v0.y);
            As[r][c+2]=tf32f(v0.z); As[r][c+3]=tf32f(v0.w);
            As[r][c+4]=tf32f(v1.x); As[r][c+5]=tf32f(v1.y);
            As[r][c+6]=tf32f(v1.z); As[r][c+7]=tf32f(v1.w);
        }
        // B
        if (TB) {
            int n = tid >> 2, c = (tid & 3) * 4;
            const float* bp = Bm + (size_t)(n0 + n) * ldb + k0 + c;
            float4 v = *(const float4*)bp;
            Bs[n][c+0]=tf32f(v.x); Bs[n][c+1]=tf32f(v.y);
            Bs[n][c+2]=tf32f(v.z); Bs[n][c+3]=tf32f(v.w);
        } else {
            int n = tid & 63, kk = tid >> 6;
            int gn = n0 + n;
            #pragma unroll
            for (int q=0;q<4;q++) {
                int gk = k0 + kk + q*4;
                float v = (gn < N) ? Bm[(size_t)gk*ldb + gn] : 0.f;
                Bs[n][kk + q*4] = tf32f(v);
            }
        }
        __syncthreads();
        #pragma unroll
        for (int kc=0; kc<16; kc+=8) {
            unsigned a0 = __float_as_uint(As[mw+g  ][kc+t4  ]);
            unsigned a1 = __float_as_uint(As[mw+g+8][kc+t4  ]);
            unsigned a2 = __float_as_uint(As[mw+g  ][kc+t4+4]);
            unsigned a3 = __float_as_uint(As[mw+g+8][kc+t4+4]);
            #pragma unroll
            for (int nt=0; nt<8; nt++) {
                unsigned b0 = __float_as_uint(Bs[nt*8+g][kc+t4  ]);
                unsigned b1 = __float_as_uint(Bs[nt*8+g][kc+t4+4]);
                mma_tf32(acc[nt], a0,a1,a2,a3, b0,b1);
            }
        }
        __syncthreads();
    }
    #pragma unroll
    for (int nt=0; nt<8; nt++) {
        #pragma unroll
        for (int e=0; e<4; e++) {
            int m = m0 + mw + g + ((e>=2)?8:0);
            int n = n0 + nt*8 + 2*t4 + (e&1);
            if (n >= N) continue;
            float v = acc[nt][e];
            if (EP == EP_TANH)      v = tanhf(v);
            else if (EP == EP_SILU) v = v / (1.f + expf(-v));
            else if (EP == EP_BIAS) v = v + bias[n];
            else if (EP == EP_MIX) {
                size_t o = (size_t)m*ldc + n;
                v = xbase[o] + dxp[o]*(maa[n] + v);
            }
            C[(size_t)m*ldc + n] = v;
        }
    }
}

// ---------------- fp32 SGEMM (kept for the decay chain: accuracy-critical) --
template<int EP, bool TB>
__global__ __launch_bounds__(256)
void sgemm_kernel(const float* __restrict__ A, int lda,
                  const float* __restrict__ Bm, int ldb,
                  float* __restrict__ C, int ldc,
                  int M, int N, int Kd,
                  const float* __restrict__ bias)
{
    __shared__ float As[16][68];
    __shared__ float Bs[16][68];
    const int tid = threadIdx.x;
    const int tx = tid & 15, ty = tid >> 4;
    const int m0 = blockIdx.y * 64, n0 = blockIdx.x * 64;
    float acc[4][4];
    #pragma unroll
    for (int i=0;i<4;i++)
        #pragma unroll
        for (int j=0;j<4;j++) acc[i][j]=0.f;

    for (int k0 = 0; k0 < Kd; k0 += 16) {
        #pragma unroll
        for (int it=0; it<4; it++) {
            int e = tid + it*256;
            int col = e & 15, row = e >> 4;
            int gm = m0 + row, gk = k0 + col;
            As[col][row] = (gm < M && gk < Kd) ? A[(size_t)gm*lda + gk] : 0.f;
        }
        #pragma unroll
        for (int it=0; it<4; it++) {
            int e = tid + it*256;
            int kk, nn;
            if (TB) { kk = e & 15; nn = e >> 4; } else { nn = e & 63; kk = e >> 6; }
            int gk = k0 + kk, gn = n0 + nn;
            float v = 0.f;
            if (gn < N && gk < Kd)
                v = TB ? Bm[(size_t)gn*ldb + gk] : Bm[(size_t)gk*ldb + gn];
            Bs[kk][nn] = v;
        }
        __syncthreads();
        #pragma unroll
        for (int kk=0; kk<16; kk++) {
            float a[4], b[4];
            #pragma unroll
            for (int i=0;i<4;i++) a[i] = As[kk][ty*4+i];
            #pragma unroll
            for (int j=0;j<4;j++) b[j] = Bs[kk][tx*4+j];
            #pragma unroll
            for (int i=0;i<4;i++)
                #pragma unroll
                for (int j=0;j<4;j++) acc[i][j] = fmaf(a[i], b[j], acc[i][j]);
        }
        __syncthreads();
    }
    #pragma unroll
    for (int i=0;i<4;i++) {
        int m = m0 + ty*4 + i;
        if (m >= M) continue;
        #pragma unroll
        for (int j=0;j<4;j++) {
            int n = n0 + tx*4 + j;
            if (n >= N) continue;
            float v = acc[i][j];
            if (EP == EP_TANH)      v = tanhf(v);
            else if (EP == EP_BIAS) v = v + bias[n];
            C[(size_t)m*ldc + n] = v;
        }
    }
}

// ---------------- per-head cumsum + exp-factor precompute (tf32-rounded) ----
__global__ __launch_bounds__(1024)
void headprep_kernel() {
    int bh = blockIdx.x;
    int b = bh >> 4, h = bh & 15;
    int tid = threadIdx.x;
    int c = tid >> 6, kx = tid & 63;
    __shared__ float csum[16][64];
    __shared__ float w512[64], shf[64], shb[64];
    const size_t ibase = (size_t)b*T_*D_ + (size_t)h*K_ + kx; // + t*D_
    float s = 0.f;
    for (int tt=0; tt<64; tt++) {
        int t = c*64 + tt;
        float wv = -expf(g_w[ibase + (size_t)t*D_]);
        if (t == 512) w512[kx] = wv;
        s += wv;
    }
    csum[c][kx] = s;
    __syncthreads();
    if (tid < 64) {
        float run = 0.f;
        #pragma unroll
        for (int cc=0; cc<16; cc++) {
            if (cc == 8) shb[tid] = run;
            float tmp = csum[cc][tid];
            csum[cc][tid] = run;        // exclusive chunk prefix
            run += tmp;
        }
        shf[tid] = shb[tid] + w512[tid];  // inclusive cumsum at t=512
    }
    __syncthreads();
    float cs = csum[c][kx];
    float sf = shf[kx], sb = shb[kx];
    size_t obase = (size_t)bh*T_*K_ + kx;
    for (int tt=0; tt<64; tt++) {
        int t = c*64 + tt;
        size_t gi = ibase + (size_t)t*D_;
        float wv = -expf(g_w[gi]);
        float cprev = cs;
        cs += wv;
        float cf = fminf(fmaxf(cs    - sf, -60.f), 60.f);
        float cb = fminf(fmaxf(cprev - sb, -60.f), 60.f);
        float rr = g_r[gi], kk = g_k[gi], vv = g_v[gi];
        size_t go = obase + (size_t)t*K_;
        g_rf[go] = tf32f(rr * expf( cf));
        g_kf[go] = tf32f(kk * expf(-cf));
        g_rb[go] = tf32f(rr * expf(-cb));
        g_kb[go] = tf32f(kk * expf( cb));
        g_vh[go] = tf32f(vv);
    }
}

// ---------------- bidirectional attention on tensor cores -------------------
__global__ __launch_bounds__(256)
void attn_mma() {
    extern __shared__ float sm[];
    typedef float row_t[68];
    row_t* Rf = (row_t*)sm;
    row_t* Rb = Rf + 64;
    row_t* Kf = Rb + 64;
    row_t* Kb = Kf + 64;
    row_t* Vt = Kb + 64;   // transposed: Vt[kdim][j]
    row_t* Ss = Vt + 64;

    int bh = blockIdx.x, it = blockIdx.y;
    int tid = threadIdx.x, lane = tid & 31, w = tid >> 5;
    int g = lane >> 2, t4 = lane & 3;
    int mi = (w & 3) * 16;         // warp's row block within tile
    int nh = (w >> 2) * 32;        // warp's col half
    size_t base = (size_t)bh * T_ * K_;
    int i0 = it * 64;

    for (int e = tid; e < 4096; e += 256) {
        int r = e >> 6, cc = e & 63;
        size_t gadr = base + (size_t)(i0 + r)*K_ + cc;
        Rf[r][cc] = g_rf[gadr];
        Rb[r][cc] = g_rb[gadr];
    }

    float o[4][4];
    #pragma unroll
    for (int i=0;i<4;i++)
        #pragma unroll
        for (int j=0;j<4;j++) o[i][j]=0.f;

    for (int jt = 0; jt < 16; jt++) {
        __syncthreads();
        int j0 = jt * 64;
        for (int e = tid; e < 4096; e += 256) {
            int r = e >> 6, cc = e & 63;
            size_t gadr = base + (size_t)(j0 + r)*K_ + cc;
            Vt[cc][r] = g_vh[gadr];
            if (jt <= it) Kf[r][cc] = g_kf[gadr];
            if (jt >= it) Kb[r][cc] = g_kb[gadr];
        }
        __syncthreads();

        float S[4][4];
        #pragma unroll
        for (int i=0;i<4;i++)
            #pragma unroll
            for (int j=0;j<4;j++) S[i][j]=0.f;

        if (jt <= it) {
            #pragma unroll
            for (int kc=0; kc<64; kc+=8) {
                unsigned a0=__float_as_uint(Rf[mi+g  ][kc+t4  ]);
                unsigned a1=__float_as_uint(Rf[mi+g+8][kc+t4  ]);
                unsigned a2=__float_as_uint(Rf[mi+g  ][kc+t4+4]);
                unsigned a3=__float_as_uint(Rf[mi+g+8][kc+t4+4]);
                #pragma unroll
                for (int nt=0; nt<4; nt++) {
                    unsigned b0=__float_as_uint(Kf[nh+nt*8+g][kc+t4  ]);
                    unsigned b1=__float_as_uint(Kf[nh+nt*8+g][kc+t4+4]);
                    mma_tf32(S[nt], a0,a1,a2,a3, b0,b1);
                }
            }
        } else {
            #pragma unroll
            for (int kc=0; kc<64; kc+=8) {
                unsigned a0=__float_as_uint(Rb[mi+g  ][kc+t4  ]);
                unsigned a1=__float_as_uint(Rb[mi+g+8][kc+t4  ]);
                unsigned a2=__float_as_uint(Rb[mi+g  ][kc+t4+4]);
                unsigned a3=__float_as_uint(Rb[mi+g+8][kc+t4+4]);
                #pragma unroll
                for (int nt=0; nt<4; nt++) {
                    unsigned b0=__float_as_uint(Kb[nh+nt*8+g][kc+t4  ]);
                    unsigned b1=__float_as_uint(Kb[nh+nt*8+g][kc+t4+4]);
                    mma_tf32(S[nt], a0,a1,a2,a3, b0,b1);
                }
            }
        }
        if (jt == it) {   // diagonal: also compute backward, per-element select
            float Sb[4][4];
            #pragma unroll
            for (int i=0;i<4;i++)
                #pragma unroll
                for (int j=0;j<4;j++) Sb[i][j]=0.f;
            #pragma unroll
            for (int kc=0; kc<64; kc+=8) {
                unsigned a0=__float_as_uint(Rb[mi+g  ][kc+t4  ]);
                unsigned a1=__float_as_uint(Rb[mi+g+8][kc+t4  ]);
                unsigned a2=__float_as_uint(Rb[mi+g  ][kc+t4+4]);
                unsigned a3=__float_as_uint(Rb[mi+g+8][kc+t4+4]);
                #pragma unroll
                for (int nt=0; nt<4; nt++) {
                    unsigned b0=__float_as_uint(Kb[nh+nt*8+g][kc+t4  ]);
                    unsigned b1=__float_as_uint(Kb[nh+nt*8+g][kc+t4+4]);
                    mma_tf32(Sb[nt], a0,a1,a2,a3, b0,b1);
                }
            }
            #pragma unroll
            for (int nt=0; nt<4; nt++)
                #pragma unroll
                for (int e=0; e<4; e++) {
                    int il = mi + g + ((e>=2)?8:0);
                    int jl = nh + nt*8 + 2*t4 + (e&1);
                    if (il < jl) S[nt][e] = Sb[nt][e];
                }
        }
        #pragma unroll
        for (int nt=0; nt<4; nt++)
            #pragma unroll
            for (int e=0; e<4; e++) {
                int il = mi + g + ((e>=2)?8:0);
                int jl = nh + nt*8 + 2*t4 + (e&1);
                Ss[il][jl] = tf32f(S[nt][e]);
            }
        __syncthreads();

        // O += S @ V  (A = Ss[i][j] row-major, B = Vt[kk][j] "col-major")
        #pragma unroll
        for (int kc=0; kc<64; kc+=8) {
            unsigned a0=__float_as_uint(Ss[mi+g  ][kc+t4  ]);
            unsigned a1=__float_as_uint(Ss[mi+g+8][kc+t4  ]);
            unsigned a2=__float_as_uint(Ss[mi+g  ][kc+t4+4]);
            unsigned a3=__float_as_uint(Ss[mi+g+8][kc+t4+4]);
            #pragma unroll
            for (int nt=0; nt<4; nt++) {
                unsigned b0=__float_as_uint(Vt[nh+nt*8+g][kc+t4  ]);
                unsigned b1=__float_as_uint(Vt[nh+nt*8+g][kc+t4+4]);
                mma_tf32(o[nt], a0,a1,a2,a3, b0,b1);
            }
        }
    }
    #pragma unroll
    for (int nt=0; nt<4; nt++)
        #pragma unroll
        for (int e=0; e<4; e++) {
            int il = mi + g + ((e>=2)?8:0);
            int jl = nh + nt*8 + 2*t4 + (e&1);
            g_yh[base + (size_t)(i0 + il)*K_ + jl] = o[nt][e];
        }
}

// ---------------- group-norm (per head, K=64) + scale/bias + gate -----------
__global__ __launch_bounds__(512)
void ln_gate_kernel(const float* __restrict__ ln_w,
                    const float* __restrict__ ln_b) {
    int row = blockIdx.x;          // b*T + t
    int b = row >> 10, t = row & (T_-1);
    int h = threadIdx.x >> 5;      // warp = head
    int lane = threadIdx.x & 31;
    size_t base = (((size_t)b*H_ + h)*T_ + t)*K_;
    float v0 = g_yh[base + lane*2];
    float v1 = g_yh[base + lane*2 + 1];
    float s = v0 + v1;
    #pragma unroll
    for (int off=16; off>0; off>>=1) s += __shfl_xor_sync(0xffffffffu, s, off);
    float mu = s * (1.f/64.f);
    float d0 = v0 - mu, d1 = v1 - mu;
    float sq = d0*d0 + d1*d1;
    #pragma unroll
    for (int off=16; off>0; off>>=1) sq += __shfl_xor_sync(0xffffffffu, sq, off);
    float inv = rsqrtf(sq*(1.f/64.f) + 6.4e-4f);
    int d = h*K_ + lane*2;
    size_t oo = (size_t)row*D_ + d;
    float y0 = (d0*inv)*ln_w[d]   + ln_b[d];
    float y1 = (d1*inv)*ln_w[d+1] + ln_b[d+1];
    g_yg[oo]   = y0 * g_gt[oo];
    g_yg[oo+1] = y1 * g_gt[oo+1];
}

// ---------------- host launch ------------------------------------------------
extern "C" void kernel_launch(void* const* d_in, const int* in_sizes, int n_in,
                              void* d_out, int out_size) {
    const float* x        = (const float*)d_in[0];
    const float* maa_x    = (const float*)d_in[1];
    const float* maa_w    = (const float*)d_in[2];
    const float* maa_k    = (const float*)d_in[3];
    const float* maa_v    = (const float*)d_in[4];
    const float* maa_r    = (const float*)d_in[5];
    const float* maa_g    = (const float*)d_in[6];
    const float* maa_w1   = (const float*)d_in[7];   // (D, 160)
    const float* maa_w2   = (const float*)d_in[8];   // (5, 32, D)
    const float* tdecay   = (const float*)d_in[9];   // (1,1,D)
    const float* dec_w1   = (const float*)d_in[10];  // (D, 64)
    const float* dec_w2   = (const float*)d_in[11];  // (64, D)
    const float* W_r      = (const float*)d_in[12];
    const float* W_k      = (const float*)d_in[13];
    const float* W_v      = (const float*)d_in[14];
    const float* W_g      = (const float*)d_in[15];
    const float* W_o      = (const float*)d_in[16];
    const float* ln_w     = (const float*)d_in[17];
    const float* ln_b     = (const float*)d_in[18];
    float* out = (float*)d_out;

    float *p_dx, *p_xmix, *p_xxx, *p_xm, *p_r, *p_k, *p_v, *p_gt, *p_w, *p_wtmp, *p_yg;
    cudaGetSymbolAddress((void**)&p_dx,   g_dx);
    cudaGetSymbolAddress((void**)&p_xmix, g_xmix);
    cudaGetSymbolAddress((void**)&p_xxx,  g_xxx);
    cudaGetSymbolAddress((void**)&p_xm,   g_xm);
    cudaGetSymbolAddress((void**)&p_r,    g_r);
    cudaGetSymbolAddress((void**)&p_k,    g_k);
    cudaGetSymbolAddress((void**)&p_v,    g_v);
    cudaGetSymbolAddress((void**)&p_gt,   g_gt);
    cudaGetSymbolAddress((void**)&p_w,    g_w);
    cudaGetSymbolAddress((void**)&p_wtmp, g_wtmp);
    cudaGetSymbolAddress((void**)&p_yg,   g_yg);

    // 1) dxprev + xmix
    prep_kernel<<<(BTD+255)/256, 256>>>(x, maa_x);

    // 2) xxx = tanh(xmix @ maa_w1)    M=4096,N=160,K=1024 (NN, tf32)
    mma_gemm<EP_TANH,false><<<dim3(3,32), 256>>>(
        p_xmix, D_, maa_w1, 160, p_xxx, 160, BT_, 160, D_,
        nullptr, nullptr, nullptr, nullptr);

    // 3) x{w,k,v,r,g} = x + dxprev*(maa_f + xxx_f @ w2_f)   (NN, K=32, tf32)
    const float* maas[5] = {maa_w, maa_k, maa_v, maa_r, maa_g};
    for (int f = 0; f < 5; f++) {
        mma_gemm<EP_MIX,false><<<dim3(16,32), 256>>>(
            p_xxx + f*32, 160, maa_w2 + (size_t)f*32*D_, D_,
            p_xm + (size_t)f*BTD, D_, BT_, D_, 32,
            nullptr, x, p_dx, maas[f]);
    }

    // 4) big projections (NT against W[D,D], tf32)
    mma_gemm<EP_NONE,true><<<dim3(16,32), 256>>>(
        p_xm + 3*(size_t)BTD, D_, W_r, D_, p_r, D_, BT_, D_, D_,
        nullptr, nullptr, nullptr, nullptr);
    mma_gemm<EP_NONE,true><<<dim3(16,32), 256>>>(
        p_xm + 1*(size_t)BTD, D_, W_k, D_, p_k, D_, BT_, D_, D_,
        nullptr, nullptr, nullptr, nullptr);
    mma_gemm<EP_NONE,true><<<dim3(16,32), 256>>>(
        p_xm + 2*(size_t)BTD, D_, W_v, D_, p_v, D_, BT_, D_, D_,
        nullptr, nullptr, nullptr, nullptr);
    mma_gemm<EP_SILU,true><<<dim3(16,32), 256>>>(
        p_xm + 4*(size_t)BTD, D_, W_g, D_, p_gt, D_, BT_, D_, D_,
        nullptr, nullptr, nullptr, nullptr);

    // 5) w = time_decay + tanh(xw @ dec_w1) @ dec_w2   (fp32 — feeds cumsum)
    sgemm_kernel<EP_TANH,false><<<dim3(1,64), 256>>>(
        p_xm + 0*(size_t)BTD, D_, dec_w1, 64, p_wtmp, 64, BT_, 64, D_,
        nullptr);
    sgemm_kernel<EP_BIAS,false><<<dim3(16,64), 256>>>(
        p_wtmp, 64, dec_w2, D_, p_w, D_, BT_, D_, 64,
        tdecay);

    // 6) cumsum + exp factors into head layout (tf32-rounded outputs)
    headprep_kernel<<<B_*H_, 1024>>>();

    // 7) bidirectional attention on tensor cores
    static const int ATTN_SMEM = 6*64*68*4;   // 104448 B
    cudaFuncSetAttribute(attn_mma,
                         cudaFuncAttributeMaxDynamicSharedMemorySize, ATTN_SMEM);
    attn_mma<<<dim3(B_*H_, 16), 256, ATTN_SMEM>>>();

    // 8) group-norm + gate
    ln_gate_kernel<<<BT_, 512>>>(ln_w, ln_b);

    // 9) out = yg @ W_o^T (tf32)
    mma_gemm<EP_NONE,true><<<dim3(16,32), 256>>>(
        p_yg, D_, W_o, D_, out, D_, BT_, D_, D_,
        nullptr, nullptr, nullptr, nullptr);
}